// round 15
// baseline (speedup 1.0000x reference)
#include <cuda_runtime.h>
#include <cuda_fp16.h>
#include <cuda_fp8.h>
#include <math.h>
#include <stdint.h>

// ---------------------------------------------------------------------------
// Problem constants
// ---------------------------------------------------------------------------
#define Bsz 4
#define Nseq 2048
#define Dm 1024
#define Hm 2048
#define QKd 128
#define Gsz 256
#define ROWS (Bsz * Nseq)          // 8192
#define NGROUPS (Bsz * (Nseq/Gsz)) // 32
#define HEADSZ ((long long)ROWS * QKd)

typedef __half fp16;
typedef unsigned char u8;

#define W_SCALE 64.f       // weights stored *64 in e4m3
#define C_SCALE 256.f      // comb stored *256 in e4m3

// ---------------------------------------------------------------------------
// Scratch (bytes)
// ---------------------------------------------------------------------------
#define OFF_NORMED8 0ull                              // e4m3 [8192][1024]   8MB
#define OFF_WH8     (OFF_NORMED8 + 8388608ull)        // e4m3 [4096][1024]   4MB
#define OFF_WQK8    (OFF_WH8     + 4194304ull)        // e4m3 [128][1024]  128KB
#define OFF_WOUT8   (OFF_WQK8    + 131072ull)         // e4m3 [1024][2048]   2MB
#define OFF_HBUF    (OFF_WOUT8   + 2097152ull)        // fp16 [8192][4096]  64MB (v | gate)
#define OFF_QKF     (OFF_HBUF    + 67108864ull)       // f32  [8192][128]    4MB
#define OFF_HEADS   (OFF_QKF     + 4194304ull)        // fp16 [4][8192][128] 8MB
#define OFF_LINKT   (OFF_HEADS   + 8388608ull)        // fp16 [4][128][2048] 2MB
#define OFF_ATTN    (OFF_LINKT   + 2097152ull)        // fp16 [32][256][256] 4MB
#define OFF_QUAD    (OFF_ATTN    + 4194304ull)        // fp16 [8192][2048]  32MB
#define OFF_LKVF    (OFF_QUAD    + 33554432ull)       // f32  [4][128][2048] 4MB
#define OFF_LKVB    (OFF_LKVF    + 4194304ull)        // fp16 [4][128][2048] 2MB
#define OFF_COMB8   (OFF_LKVB    + 2097152ull)        // e4m3 [8192][2048]  16MB
#define SCR_BYTES   (OFF_COMB8   + 16777216ull)

__device__ __align__(256) unsigned char g_scr[SCR_BYTES];

// ---------------------------------------------------------------------------
// PTX helpers
// ---------------------------------------------------------------------------
__device__ __forceinline__ uint32_t smem_u32(const void* p) {
    uint32_t a;
    asm("{ .reg .u64 t; cvta.to.shared.u64 t, %1; cvt.u32.u64 %0, t; }"
        : "=r"(a) : "l"(p));
    return a;
}
__device__ __forceinline__ void cpasync16(uint32_t s, const void* g) {
    asm volatile("cp.async.cg.shared.global [%0], [%1], 16;\n" :: "r"(s), "l"(g));
}
__device__ __forceinline__ void cp_commit() { asm volatile("cp.async.commit_group;\n"); }

__device__ __forceinline__ void ldsm4(uint32_t r[4], uint32_t a) {
    asm volatile("ldmatrix.sync.aligned.m8n8.x4.shared.b16 {%0,%1,%2,%3}, [%4];\n"
                 : "=r"(r[0]), "=r"(r[1]), "=r"(r[2]), "=r"(r[3]) : "r"(a));
}
__device__ __forceinline__ void ldsm4t(uint32_t r[4], uint32_t a) {
    asm volatile("ldmatrix.sync.aligned.m8n8.x4.trans.shared.b16 {%0,%1,%2,%3}, [%4];\n"
                 : "=r"(r[0]), "=r"(r[1]), "=r"(r[2]), "=r"(r[3]) : "r"(a));
}
// fp16 inputs, fp16 accumulate
__device__ __forceinline__ void mma16816h(uint32_t c[2], const uint32_t a[4],
                                          uint32_t b0, uint32_t b1) {
    asm volatile("mma.sync.aligned.m16n8k16.row.col.f16.f16.f16.f16 "
                 "{%0,%1}, {%2,%3,%4,%5}, {%6,%7}, {%0,%1};\n"
                 : "+r"(c[0]), "+r"(c[1])
                 : "r"(a[0]), "r"(a[1]), "r"(a[2]), "r"(a[3]), "r"(b0), "r"(b1));
}
// e4m3 inputs, fp32 accumulate: 4096 MAC/instr
__device__ __forceinline__ void mma16832f8(float c[4], const uint32_t a[4],
                                           uint32_t b0, uint32_t b1) {
    asm volatile("mma.sync.aligned.m16n8k32.row.col.f32.e4m3.e4m3.f32 "
                 "{%0,%1,%2,%3}, {%4,%5,%6,%7}, {%8,%9}, {%0,%1,%2,%3};\n"
                 : "+f"(c[0]), "+f"(c[1]), "+f"(c[2]), "+f"(c[3])
                 : "r"(a[0]), "r"(a[1]), "r"(a[2]), "r"(a[3]), "r"(b0), "r"(b1));
}

// Conflict-free swizzles (byte offsets; rows of 64 / 256 bytes).
__device__ __forceinline__ uint32_t swz64(int r, int cb) {
    return (uint32_t)(r * 64 + ((((cb >> 4) ^ ((r >> 1) & 3)) << 4) | (cb & 15)));
}
__device__ __forceinline__ uint32_t swz256(int k, int nb) {
    int ch = nb >> 4;
    ch = (ch & 8) | ((ch ^ k) & 7);
    return (uint32_t)(k * 256 + (ch << 4) + (nb & 15));
}

// ---------------------------------------------------------------------------
// LayerNorm (fp32 in, e4m3 out)
// ---------------------------------------------------------------------------
__global__ void layernorm_kernel(const float* __restrict__ x,
                                 const float* __restrict__ g,
                                 const float* __restrict__ b,
                                 u8* __restrict__ out) {
    long long row = blockIdx.x;
    int t = threadIdx.x;
    float4 v = ((const float4*)(x + row * Dm))[t];
    float s  = v.x + v.y + v.z + v.w;
    float sq = v.x*v.x + v.y*v.y + v.z*v.z + v.w*v.w;
    #pragma unroll
    for (int o = 16; o; o >>= 1) {
        s  += __shfl_xor_sync(0xffffffffu, s,  o);
        sq += __shfl_xor_sync(0xffffffffu, sq, o);
    }
    __shared__ float ss[8], sqs[8];
    if ((t & 31) == 0) { ss[t >> 5] = s; sqs[t >> 5] = sq; }
    __syncthreads();
    if (t < 32) {
        float a  = (t < 8) ? ss[t]  : 0.f;
        float a2 = (t < 8) ? sqs[t] : 0.f;
        #pragma unroll
        for (int o = 4; o; o >>= 1) {
            a  += __shfl_xor_sync(0xffffffffu, a,  o);
            a2 += __shfl_xor_sync(0xffffffffu, a2, o);
        }
        if (t == 0) { ss[0] = a; sqs[0] = a2; }
    }
    __syncthreads();
    float mean = ss[0] * (1.f / Dm);
    float var  = sqs[0] * (1.f / Dm) - mean * mean;
    float inv  = rsqrtf(var + 1e-5f);
    float4 gg = ((const float4*)g)[t];
    float4 bb = ((const float4*)b)[t];
    float o0 = (v.x - mean) * inv * gg.x + bb.x;
    float o1 = (v.y - mean) * inv * gg.y + bb.y;
    float o2 = (v.z - mean) * inv * gg.z + bb.z;
    float o3 = (v.w - mean) * inv * gg.w + bb.w;
    __nv_fp8x4_e4m3 p(make_float4(o0, o1, o2, o3));
    ((uint32_t*)(out + row * Dm))[t] = *(uint32_t*)&p;
}

// ---------------------------------------------------------------------------
// Weight transpose+convert: f32 [R][C] -> e4m3 [C][R] * W_SCALE
// ---------------------------------------------------------------------------
__global__ void wtrans8(const float* __restrict__ in, u8* __restrict__ out,
                        int R, int C) {
    __shared__ float tile[32][33];
    int c0 = blockIdx.x * 32, r0 = blockIdx.y * 32;
    int tx = threadIdx.x, ty = threadIdx.y;
    #pragma unroll
    for (int i = ty; i < 32; i += 8)
        tile[i][tx] = in[(long long)(r0 + i) * C + c0 + tx];
    __syncthreads();
    #pragma unroll
    for (int i = ty; i < 32; i += 8) {
        __nv_fp8_e4m3 q(tile[tx][i] * W_SCALE);
        out[(long long)(c0 + i) * R + r0 + tx] = *(u8*)&q;
    }
}

// ---------------------------------------------------------------------------
// fp32 -> fp16 (vectorized by 4)
// ---------------------------------------------------------------------------
__global__ void f2h_kernel(const float* __restrict__ in, fp16* __restrict__ out, int n4) {
    int i = blockIdx.x * blockDim.x + threadIdx.x;
    if (i < n4) {
        float4 v = ((const float4*)in)[i];
        ((__half2*)out)[2*i]   = __floats2half2_rn(v.x, v.y);
        ((__half2*)out)[2*i+1] = __floats2half2_rn(v.z, v.w);
    }
}

// ---------------------------------------------------------------------------
// OffsetScale + RoPE (fp32 math; fp16 out). Also writes lin_k transposed.
// ---------------------------------------------------------------------------
__global__ void rope_kernel(const float* __restrict__ qk,
                            const float* __restrict__ b_qk,
                            const float* __restrict__ gamma,
                            const float* __restrict__ beta,
                            fp16* __restrict__ heads,
                            fp16* __restrict__ linkT) {
    int row = blockIdx.x;
    int h = threadIdx.x >> 6;
    int j = threadIdx.x & 63;
    __shared__ float s[QKd];
    __shared__ float sc[64], ss_[64];
    if (threadIdx.x < QKd) {
        float z = qk[(long long)row * QKd + threadIdx.x] + b_qk[threadIdx.x];
        s[threadIdx.x] = z / (1.f + expf(-z));
    }
    if (threadIdx.x < 64) {
        int pos = row & (Nseq - 1);
        float invf = powf(10000.0f, (float)threadIdx.x * (1.0f / 64.0f));
        float th = (float)pos * invf;
        sc[threadIdx.x]  = cosf(th);
        ss_[threadIdx.x] = sinf(th);
    }
    __syncthreads();
    float a1 = s[j]      * gamma[h * QKd + j]      + beta[h * QKd + j];
    float a2 = s[j + 64] * gamma[h * QKd + j + 64] + beta[h * QKd + j + 64];
    float cs = sc[j], sn = ss_[j];
    float r1 = a1 * cs - a2 * sn;
    float r2 = a2 * cs + a1 * sn;
    long long base = ((long long)h * ROWS + row) * QKd;
    heads[base + j]      = __float2half_rn(r1);
    heads[base + j + 64] = __float2half_rn(r2);
    if (h == 3) {
        int batch = row >> 11;
        int pos   = row & (Nseq - 1);
        long long tb = (long long)batch * QKd * Nseq;
        linkT[tb + (long long)j * Nseq + pos]        = __float2half_rn(r1);
        linkT[tb + (long long)(j + 64) * Nseq + pos] = __float2half_rn(r2);
    }
}

#define EPI_SILU    0
#define EPI_RELU2   1
#define EPI_STOREB  2
#define EPI_ATOMIC  3
#define EPI_COMBINE 4
#define EPI_FINAL   5

#define STAGES 3
#define SMEM_GM (STAGES * 2 * 8192)     // 48KB

// ---------------------------------------------------------------------------
// FP8 GEMM: 128x128x64B CTA tile, 8 warps (4x2), 32x64 warp tiles, fp32 acc.
// A row-major [M][K] e4m3; B [N][K] e4m3 (C = A * B^T).
// ---------------------------------------------------------------------------
template<int EPI>
__global__ __launch_bounds__(256)
void gemm_fp8(const u8* __restrict__ A, const u8* __restrict__ B,
              void* __restrict__ Cv,
              int lda, int ldb, int ldc,
              int kchunk, int nk,
              float scale,
              const float* __restrict__ bias,
              const float* __restrict__ xres, int ldx) {
    extern __shared__ unsigned char smem[];
    const uint32_t aSm = smem_u32(smem);
    const uint32_t bSm = aSm + STAGES * 8192;

    const int tid = threadIdx.x;
    const int kc = blockIdx.z;           // split-K index (nk chunks)
    A += (long long)kc * kchunk;
    B += (long long)kc * kchunk;
    const int m0 = blockIdx.y * 128, n0 = blockIdx.x * 128;

    const int lane = tid & 31, wid = tid >> 5;
    const int wm = wid & 3, wn = wid >> 2;    // 32x64 warp tile

    float acc[2][8][4];
    #pragma unroll
    for (int i = 0; i < 2; i++)
        #pragma unroll
        for (int j = 0; j < 8; j++)
            #pragma unroll
            for (int q = 0; q < 4; q++) acc[i][j][q] = 0.f;

    const int iters = kchunk / 64;
    const int ar = tid >> 2, acb = (tid & 3) * 16;   // rows 0..63 (+64), 16B chunk

    auto load_stage = [&](int st, int k0) {
        const uint32_t aDst = aSm + st * 8192;
        const u8* ga = A + (long long)(m0 + ar) * lda + k0 + acb;
        cpasync16(aDst + swz64(ar, acb), ga);
        cpasync16(aDst + swz64(ar + 64, acb), ga + 64ll * lda);
        const uint32_t bDst = bSm + st * 8192;
        const u8* gb = B + (long long)(n0 + ar) * ldb + k0 + acb;
        cpasync16(bDst + swz64(ar, acb), gb);
        cpasync16(bDst + swz64(ar + 64, acb), gb + 64ll * ldb);
        cp_commit();
    };

    load_stage(0, 0);
    if (iters > 1) load_stage(1, 64);

    for (int it = 0; it < iters; ++it) {
        if (it + 1 < iters) asm volatile("cp.async.wait_group 1;\n" ::: "memory");
        else                asm volatile("cp.async.wait_group 0;\n" ::: "memory");
        __syncthreads();
        if (it + 2 < iters) load_stage((it + 2) % STAGES, (it + 2) * 64);

        const int st = it % STAGES;
        const uint32_t aB = aSm + st * 8192;
        const uint32_t bB = bSm + st * 8192;
        #pragma unroll
        for (int ks = 0; ks < 2; ++ks) {        // two k32 steps per 64B chunk
            uint32_t a[2][4];
            #pragma unroll
            for (int mi = 0; mi < 2; ++mi) {
                int r = wm * 32 + mi * 16 + (lane & 15);
                ldsm4(a[mi], aB + swz64(r, ks * 32 + (lane >> 4) * 16));
            }
            uint32_t b[4][4];
            #pragma unroll
            for (int nb = 0; nb < 4; ++nb) {
                int r = wn * 64 + nb * 16 + (lane & 7) + (lane >> 4) * 8;
                int cb = ks * 32 + ((lane >> 3) & 1) * 16;
                ldsm4(b[nb], bB + swz64(r, cb));
            }
            #pragma unroll
            for (int mi = 0; mi < 2; ++mi)
                #pragma unroll
                for (int nb = 0; nb < 4; ++nb) {
                    mma16832f8(acc[mi][2 * nb],     a[mi], b[nb][0], b[nb][1]);
                    mma16832f8(acc[mi][2 * nb + 1], a[mi], b[nb][2], b[nb][3]);
                }
        }
    }

    // epilogue
    #pragma unroll
    for (int mi = 0; mi < 2; ++mi)
        #pragma unroll
        for (int r2 = 0; r2 < 2; ++r2) {
            int row = m0 + wm * 32 + mi * 16 + (lane >> 2) + r2 * 8;
            #pragma unroll
            for (int nb = 0; nb < 8; ++nb) {
                int col = n0 + wn * 64 + nb * 8 + (lane & 3) * 2;
                float v0 = acc[mi][nb][r2 * 2]     * scale;
                float v1 = acc[mi][nb][r2 * 2 + 1] * scale;
                long long idx = (long long)row * ldc + col;
                if (EPI == EPI_SILU) {
                    v0 += bias[col]; v1 += bias[col + 1];
                    v0 = v0 / (1.f + expf(-v0));
                    v1 = v1 / (1.f + expf(-v1));
                    *(__half2*)((fp16*)Cv + idx) = __floats2half2_rn(v0, v1);
                } else if (EPI == EPI_ATOMIC) {
                    atomicAdd((float*)Cv + idx, v0);
                    atomicAdd((float*)Cv + idx + 1, v1);
                } else if (EPI == EPI_FINAL) {
                    v0 += bias[col] + xres[(long long)row * ldx + col];
                    v1 += bias[col + 1] + xres[(long long)row * ldx + col + 1];
                    *(float2*)((float*)Cv + idx) = make_float2(v0, v1);
                }
            }
        }
}

// ---------------------------------------------------------------------------
// FP16 GEMM: 128x128x32 CTA tile, 4 warps (2x2), 64x64 warp tiles, fp16 accum.
// A row-major [M][K]. BL=0: B stored [K][N]; BL=1: B stored [N][K].
// ---------------------------------------------------------------------------
template<int EPI, int BL>
__global__ __launch_bounds__(128, 3)
void gemm_fp16(const fp16* __restrict__ A, const fp16* __restrict__ B,
               void* __restrict__ Cv,
               int lda, int ldb, int ldc,
               int kchunk, int nk,
               long long sA, long long sB, long long sC,
               float scale,
               const float* __restrict__ bias,
               const fp16* __restrict__ ep0, long long s0, int ld0,
               const fp16* __restrict__ ep1, long long s1, int ld1,
               const float* __restrict__ xres, int ldx) {
    extern __shared__ unsigned char smem[];
    const uint32_t aSm = smem_u32(smem);
    const uint32_t bSm = aSm + STAGES * 8192;

    const int tid = threadIdx.x;
    const int z = blockIdx.z;
    const int batch = z / nk, kc = z - batch * nk;
    A += batch * sA + (long long)kc * kchunk;
    if (BL == 0) B += batch * sB + (long long)kc * kchunk * ldb;
    else         B += batch * sB + (long long)kc * kchunk;
    const int m0 = blockIdx.y * 128, n0 = blockIdx.x * 128;

    const int lane = tid & 31, wid = tid >> 5;
    const int wm = wid & 1, wn = wid >> 1;

    uint32_t acc[4][8][2];
    #pragma unroll
    for (int i = 0; i < 4; i++)
        #pragma unroll
        for (int j = 0; j < 8; j++) { acc[i][j][0] = 0u; acc[i][j][1] = 0u; }

    const int iters = kchunk / 32;
    const int ar  = tid >> 2, acb = (tid & 3) * 16;
    const int b0k = tid >> 4, b0n = (tid & 15) * 16;

    auto load_stage = [&](int st, int k0) {
        const uint32_t aDst = aSm + st * 8192;
        const fp16* ga = A + (long long)(m0 + ar) * lda + k0 + (acb >> 1);
        #pragma unroll
        for (int q = 0; q < 4; q++)
            cpasync16(aDst + swz64(ar + q * 32, acb), ga + (long long)(q * 32) * lda);
        const uint32_t bDst = bSm + st * 8192;
        if (BL == 0) {
            const fp16* gb = B + (long long)(k0 + b0k) * ldb + n0 + (b0n >> 1);
            #pragma unroll
            for (int q = 0; q < 4; q++)
                cpasync16(bDst + swz256(b0k + q * 8, b0n), gb + (long long)(q * 8) * ldb);
        } else {
            const fp16* gb = B + (long long)(n0 + ar) * ldb + k0 + (acb >> 1);
            #pragma unroll
            for (int q = 0; q < 4; q++)
                cpasync16(bDst + swz64(ar + q * 32, acb), gb + (long long)(q * 32) * ldb);
        }
        cp_commit();
    };

    load_stage(0, 0);
    if (iters > 1) load_stage(1, 32);

    for (int it = 0; it < iters; ++it) {
        if (it + 1 < iters) asm volatile("cp.async.wait_group 1;\n" ::: "memory");
        else                asm volatile("cp.async.wait_group 0;\n" ::: "memory");
        __syncthreads();
        if (it + 2 < iters) load_stage((it + 2) % STAGES, (it + 2) * 32);

        const int st = it % STAGES;
        const uint32_t aB = aSm + st * 8192;
        const uint32_t bB = bSm + st * 8192;
        #pragma unroll
        for (int ks = 0; ks < 2; ++ks) {
            uint32_t a[4][4];
            #pragma unroll
            for (int mi = 0; mi < 4; ++mi) {
                int r = wm * 64 + mi * 16 + (lane & 15);
                ldsm4(a[mi], aB + swz64(r, ks * 32 + (lane >> 4) * 16));
            }
            uint32_t b[4][4];
            #pragma unroll
            for (int nb = 0; nb < 4; ++nb) {
                if (BL == 0) {
                    int k = ks * 16 + (lane & 15);
                    int nbyte = (wn * 64 + nb * 16 + (lane >> 4) * 8) * 2;
                    ldsm4t(b[nb], bB + swz256(k, nbyte));
                } else {
                    int r = wn * 64 + nb * 16 + (lane & 7) + (lane >> 4) * 8;
                    int cb = (ks * 16 + ((lane >> 3) & 1) * 8) * 2;
                    ldsm4(b[nb], bB + swz64(r, cb));
                }
            }
            #pragma unroll
            for (int mi = 0; mi < 4; ++mi)
                #pragma unroll
                for (int nb = 0; nb < 4; ++nb) {
                    mma16816h(acc[mi][2 * nb],     a[mi], b[nb][0], b[nb][1]);
                    mma16816h(acc[mi][2 * nb + 1], a[mi], b[nb][2], b[nb][3]);
                }
        }
    }

    // epilogue
    #pragma unroll
    for (int mi = 0; mi < 4; ++mi)
        #pragma unroll
        for (int r2 = 0; r2 < 2; ++r2) {
            int row = m0 + wm * 64 + mi * 16 + (lane >> 2) + r2 * 8;
            #pragma unroll
            for (int nb = 0; nb < 8; ++nb) {
                int col = n0 + wn * 64 + nb * 8 + (lane & 3) * 2;
                float2 vf = __half22float2(*(__half2*)&acc[mi][nb][r2]);
                float v0 = vf.x * scale;
                float v1 = vf.y * scale;
                long long idx = batch * sC + (long long)row * ldc + col;
                if (EPI == EPI_RELU2) {
                    float r0 = v0 > 0.f ? v0 : 0.f;
                    float r1 = v1 > 0.f ? v1 : 0.f;
                    *(__half2*)((fp16*)Cv + idx) = __floats2half2_rn(r0 * r0, r1 * r1);
                } else if (EPI == EPI_STOREB) {
                    *(__half2*)((fp16*)Cv + idx) = __floats2half2_rn(v0, v1);
                } else if (EPI == EPI_ATOMIC) {
                    atomicAdd((float*)Cv + idx, v0);
                    atomicAdd((float*)Cv + idx + 1, v1);
                } else if (EPI == EPI_COMBINE) {
                    __half2 g2 = *(const __half2*)(ep0 + batch * s0 + (long long)row * ld0 + col);
                    __half2 q2 = *(const __half2*)(ep1 + batch * s1 + (long long)row * ld1 + col);
                    float2 gf = __half22float2(g2);
                    float2 qf = __half22float2(q2);
                    float o0 = gf.x * (qf.x + v0) * C_SCALE;
                    float o1 = gf.y * (qf.y + v1) * C_SCALE;
                    __nv_fp8x2_e4m3 p2(make_float2(o0, o1));
                    *(unsigned short*)((u8*)Cv + idx) = *(unsigned short*)&p2;
                }
            }
        }
}

// ---------------------------------------------------------------------------
// launch
// ---------------------------------------------------------------------------
extern "C" void kernel_launch(void* const* d_in, const int* in_sizes, int n_in,
                              void* d_out, int out_size) {
    const float* x        = (const float*)d_in[0];
    const float* ln_g     = (const float*)d_in[1];
    const float* ln_b     = (const float*)d_in[2];
    const float* W_hidden = (const float*)d_in[3];
    const float* b_hidden = (const float*)d_in[4];
    const float* W_qk     = (const float*)d_in[5];
    const float* b_qk     = (const float*)d_in[6];
    const float* os_gamma = (const float*)d_in[7];
    const float* os_beta  = (const float*)d_in[8];
    const float* W_out    = (const float*)d_in[9];
    const float* b_out    = (const float*)d_in[10];
    float* out = (float*)d_out;

    unsigned char* S = nullptr;
    cudaGetSymbolAddress((void**)&S, g_scr);
    u8*    normed8 = (u8*)(S + OFF_NORMED8);
    u8*    Wh8     = (u8*)(S + OFF_WH8);
    u8*    Wqk8    = (u8*)(S + OFF_WQK8);
    u8*    Wout8   = (u8*)(S + OFF_WOUT8);
    fp16*  hbuf    = (fp16*)(S + OFF_HBUF);    // [8192][4096]: v | gate
    float* qkf     = (float*)(S + OFF_QKF);
    fp16*  heads   = (fp16*)(S + OFF_HEADS);
    fp16*  linkT   = (fp16*)(S + OFF_LINKT);
    fp16*  attn    = (fp16*)(S + OFF_ATTN);
    fp16*  quad    = (fp16*)(S + OFF_QUAD);
    float* lkvf    = (float*)(S + OFF_LKVF);
    fp16*  lkvb    = (fp16*)(S + OFF_LKVB);
    u8*    comb8   = (u8*)(S + OFF_COMB8);

    // weight transposes -> e4m3 * W_SCALE, [N][K] layout
    wtrans8<<<dim3(4096/32, 1024/32), dim3(32, 8)>>>(W_hidden, Wh8, 1024, 4096);
    wtrans8<<<dim3(128/32,  1024/32), dim3(32, 8)>>>(W_qk,     Wqk8, 1024, 128);
    wtrans8<<<dim3(1024/32, 2048/32), dim3(32, 8)>>>(W_out,    Wout8, 2048, 1024);

    // LayerNorm -> e4m3
    layernorm_kernel<<<ROWS, 256>>>(x, ln_g, ln_b, normed8);

    // zero split-K accumulators
    cudaMemsetAsync(qkf,  0, (size_t)ROWS * QKd * sizeof(float), 0);
    cudaMemsetAsync(lkvf, 0, (size_t)Bsz * QKd * Hm * sizeof(float), 0);

    // 2) hidden (FP8): hbuf = silu(normed @ Wh + b)     [8192 x 4096 x 1024]
    gemm_fp8<EPI_SILU><<<dim3(2 * Hm / 128, ROWS / 128, 1), 256, SMEM_GM>>>(
        normed8, Wh8, hbuf, Dm, Dm, 2 * Hm, Dm, 1, 1.f / W_SCALE,
        b_hidden, nullptr, 0);

    // 3) qk (FP8, split-K=4, fp32 atomics)              [8192 x 128 x 1024]
    gemm_fp8<EPI_ATOMIC><<<dim3(1, ROWS / 128, 4), 256, SMEM_GM>>>(
        normed8, Wqk8, qkf, Dm, Dm, QKd, Dm / 4, 4, 1.f / W_SCALE,
        nullptr, nullptr, 0);

    // 4) OffsetScale + RoPE
    rope_kernel<<<ROWS, 256>>>(qkf, b_qk, os_gamma, os_beta, heads, linkT);

    // 5) attn = relu(QqKq^T / G)^2   per group           [256 x 256 x 128] x32
    gemm_fp16<EPI_RELU2, 1><<<dim3(2, 2, NGROUPS), 128, SMEM_GM>>>(
        heads + 0 * HEADSZ, heads + 2 * HEADSZ, attn, QKd, QKd, Gsz, QKd, 1,
        (long long)Gsz * QKd, (long long)Gsz * QKd, (long long)Gsz * Gsz, 1.f / Gsz,
        nullptr, nullptr, 0, 0, nullptr, 0, 0, nullptr, 0);

    // 6) quad = attn @ v   per group                      [256 x 2048 x 256] x32
    gemm_fp16<EPI_STOREB, 0><<<dim3(Hm / 128, 2, NGROUPS), 128, SMEM_GM>>>(
        attn, hbuf, quad, Gsz, 2 * Hm, Hm, Gsz, 1,
        (long long)Gsz * Gsz, (long long)Gsz * 2 * Hm, (long long)Gsz * Hm, 1.f,
        nullptr, nullptr, 0, 0, nullptr, 0, 0, nullptr, 0);

    // 7) lin_kv = (lin_k^T @ v) / N   per batch, split-K=4  [128 x 2048 x 2048] x4
    gemm_fp16<EPI_ATOMIC, 0><<<dim3(Hm / 128, 1, Bsz * 4), 128, SMEM_GM>>>(
        linkT, hbuf, lkvf, Nseq, 2 * Hm, Hm, Nseq / 4, 4,
        (long long)QKd * Nseq, (long long)Nseq * 2 * Hm, (long long)QKd * Hm, 1.f / Nseq,
        nullptr, nullptr, 0, 0, nullptr, 0, 0, nullptr, 0);
    f2h_kernel<<<(Bsz * QKd * Hm / 4 + 255) / 256, 256>>>(lkvf, lkvb, Bsz * QKd * Hm / 4);

    // 8) comb8 = e4m3(C_SCALE * gate * (quad + lin_q @ lin_kv))  [2048 x 2048 x 128] x4
    gemm_fp16<EPI_COMBINE, 0><<<dim3(Hm / 128, Nseq / 128, Bsz), 128, SMEM_GM>>>(
        heads + 1 * HEADSZ, lkvb, comb8, QKd, Hm, Hm, QKd, 1,
        (long long)Nseq * QKd, (long long)QKd * Hm, (long long)Nseq * Hm, 1.f,
        nullptr,
        hbuf + Hm, (long long)Nseq * 2 * Hm, 2 * Hm,    // gate
        quad,      (long long)Nseq * Hm,     Hm,        // quad_out
        nullptr, 0);

    // 9) out (FP8) = comb @ W_out + b_out + x             [8192 x 1024 x 2048]
    gemm_fp8<EPI_FINAL><<<dim3(Dm / 128, ROWS / 128, 1), 256, SMEM_GM>>>(
        comb8, Wout8, out, Hm, Hm, Dm, Hm, 1, 1.f / (W_SCALE * C_SCALE),
        b_out, x, Dm);
}